// round 11
// baseline (speedup 1.0000x reference)
// R11 = R8 resubmitted unchanged (4th attempt): R8/R9/R10 all died at GPU
// *acquisition* (broker pool saturated) — the failure precedes compilation, so
// kernel content is irrelevant to it. The R8 change-set (pre-split activations,
// fused QKV gemm, 128-row finalize) remains unmeasured; holding it stable for
// clean attribution.
#include <cuda_runtime.h>
#include <cuda_bf16.h>
#include <math.h>
#include <stdint.h>

#define B_   4
#define T_   2048
#define C_   1024
#define HQ_  16
#define HKV_ 4
#define D_   64
#define G_   4
#define N_   (B_*T_)        // 8192 rows
#define KVC_ (HKV_*D_)      // 256
#define QKV_ (C_+2*KVC_)    // 1536 concatenated proj cols
#define PAD  68             // attention smem row stride (floats)
#define GKP  40             // gemm smem row stride in bf16 elems

// ---------------- scratch (no allocations allowed) ----------------
__device__ float g_Q[(size_t)N_*C_];
__device__ float g_K[(size_t)N_*KVC_];
__device__ float g_V[(size_t)N_*KVC_];
__device__ float g_M[B_*HQ_*T_];
__device__ float g_L[B_*HQ_*T_];
__device__ float g_bcat[QKV_];
// pre-split activations / Y
__device__ __nv_bfloat16 g_Xh[(size_t)N_*C_], g_Xl[(size_t)N_*C_];
__device__ __nv_bfloat16 g_Yh[(size_t)N_*C_], g_Yl[(size_t)N_*C_];
// pre-transposed + bf16-split weights: QKV concatenated [1536][1024], Wo [1024][1024]
__device__ __nv_bfloat16 g_Wch[(size_t)QKV_*C_], g_Wcl[(size_t)QKV_*C_];
__device__ __nv_bfloat16 g_Woh[(size_t)C_*C_],   g_Wol[(size_t)C_*C_];

// ---------------- mma helpers ----------------
__device__ __forceinline__ void mma_tf32(float c[4],
    uint32_t a0, uint32_t a1, uint32_t a2, uint32_t a3,
    uint32_t b0, uint32_t b1)
{
    asm volatile(
        "mma.sync.aligned.m16n8k8.row.col.f32.tf32.tf32.f32 "
        "{%0,%1,%2,%3}, {%4,%5,%6,%7}, {%8,%9}, {%0,%1,%2,%3};\n"
        : "+f"(c[0]), "+f"(c[1]), "+f"(c[2]), "+f"(c[3])
        : "r"(a0), "r"(a1), "r"(a2), "r"(a3), "r"(b0), "r"(b1));
}
__device__ __forceinline__ void mma_bf16(float c[4],
    uint32_t a0, uint32_t a1, uint32_t a2, uint32_t a3,
    uint32_t b0, uint32_t b1)
{
    asm volatile(
        "mma.sync.aligned.m16n8k16.row.col.f32.bf16.bf16.f32 "
        "{%0,%1,%2,%3}, {%4,%5,%6,%7}, {%8,%9}, {%0,%1,%2,%3};\n"
        : "+f"(c[0]), "+f"(c[1]), "+f"(c[2]), "+f"(c[3])
        : "r"(a0), "r"(a1), "r"(a2), "r"(a3), "r"(b0), "r"(b1));
}
__device__ __forceinline__ float tf32rn(float x)
{
    uint32_t u;
    asm("cvt.rna.tf32.f32 %0, %1;" : "=r"(u) : "f"(x));
    return __uint_as_float(u);
}
__device__ __forceinline__ uint32_t pack_bf2(float x, float y)
{
    __nv_bfloat162 t = __floats2bfloat162_rn(x, y);
    return *(uint32_t*)&t;
}

// ---------------- x -> bf16 hi/lo split ----------------
__global__ __launch_bounds__(256) void split_x(const float* __restrict__ X,
                                               __nv_bfloat16* __restrict__ Xh,
                                               __nv_bfloat16* __restrict__ Xl)
{
    const int idx = blockIdx.x * 256 + threadIdx.x;      // float4 index
    float4 v = ((const float4*)X)[idx];
    float hx = __bfloat162float(__float2bfloat16_rn(v.x));
    float hy = __bfloat162float(__float2bfloat16_rn(v.y));
    float hz = __bfloat162float(__float2bfloat16_rn(v.z));
    float hw = __bfloat162float(__float2bfloat16_rn(v.w));
    uint2 h = make_uint2(pack_bf2(hx, hy), pack_bf2(hz, hw));
    uint2 l = make_uint2(pack_bf2(v.x - hx, v.y - hy), pack_bf2(v.z - hz, v.w - hw));
    ((uint2*)Xh)[idx] = h;
    ((uint2*)Xl)[idx] = l;
}

// ---------------- weight prep: transpose + bf16 hi/lo split ----------------
__global__ void transpose_split(const float* __restrict__ W,
                                __nv_bfloat16* __restrict__ Th,
                                __nv_bfloat16* __restrict__ Tl,
                                int K, int N)
{
    __shared__ float s[32][33];
    const int n0 = blockIdx.x * 32, k0 = blockIdx.y * 32;
    const int tx = threadIdx.x, ty = threadIdx.y;
#pragma unroll
    for (int i = 0; i < 32; i += 8)
        s[ty + i][tx] = W[(size_t)(k0 + ty + i) * N + n0 + tx];
    __syncthreads();
#pragma unroll
    for (int i = 0; i < 32; i += 8) {
        float v = s[tx][ty + i];
        __nv_bfloat16 h = __float2bfloat16_rn(v);
        __nv_bfloat16 l = __float2bfloat16_rn(v - __bfloat162float(h));
        Th[(size_t)(n0 + ty + i) * K + k0 + tx] = h;
        Tl[(size_t)(n0 + ty + i) * K + k0 + tx] = l;
    }
}

// ---------------- shared GEMM mainloop (pre-split A and B, bf16x3) ----------------
// 128x128x32 tile, 256 thr, acc[2][8][4] per thread. K = 1024 fixed.
#define GEMM_CORE(Ath, Atl, Bth, Btl)                                             \
    __shared__ __nv_bfloat16 Ah[128 * GKP], Al[128 * GKP];                        \
    __shared__ __nv_bfloat16 Bh[128 * GKP], Bl[128 * GKP];                        \
    uint32_t* Ahu = (uint32_t*)Ah;  uint32_t* Alu = (uint32_t*)Al;                \
    uint32_t* Bhu = (uint32_t*)Bh;  uint32_t* Blu = (uint32_t*)Bl;                \
    const int tid  = threadIdx.x;                                                 \
    const int w    = tid >> 5;                                                    \
    const int lane = tid & 31;                                                    \
    const int gid  = lane >> 2;                                                   \
    const int tig  = lane & 3;                                                    \
    const int mw   = w & 3;                                                       \
    const int nw   = w >> 2;                                                      \
    const int cB0  = nw * 64;                                                     \
    float acc[2][8][4];                                                           \
    _Pragma("unroll")                                                             \
    for (int m = 0; m < 2; m++)                                                   \
        _Pragma("unroll")                                                         \
        for (int n = 0; n < 8; n++)                                               \
            _Pragma("unroll")                                                     \
            for (int e = 0; e < 4; e++) acc[m][n][e] = 0.f;                       \
    for (int k0 = 0; k0 < 1024; k0 += 32) {                                       \
        _Pragma("unroll")                                                         \
        for (int i = 0; i < 2; i++) {                                             \
            int idx8 = tid + i * 256;                                             \
            int r = idx8 >> 2, k8 = (idx8 & 3) << 3;                              \
            *(uint4*)&Ahu[r * (GKP/2) + (k8 >> 1)] =                              \
                *(const uint4*)&Ath[(size_t)(row0 + r) * 1024 + k0 + k8];         \
            *(uint4*)&Alu[r * (GKP/2) + (k8 >> 1)] =                              \
                *(const uint4*)&Atl[(size_t)(row0 + r) * 1024 + k0 + k8];         \
            *(uint4*)&Bhu[r * (GKP/2) + (k8 >> 1)] =                              \
                *(const uint4*)&Bth[(size_t)(col0 + r) * 1024 + k0 + k8];         \
            *(uint4*)&Blu[r * (GKP/2) + (k8 >> 1)] =                              \
                *(const uint4*)&Btl[(size_t)(col0 + r) * 1024 + k0 + k8];         \
        }                                                                         \
        __syncthreads();                                                          \
        _Pragma("unroll")                                                         \
        for (int kk = 0; kk < 32; kk += 16) {                                     \
            const int kw = (kk >> 1) + tig;                                       \
            uint32_t ah[2][4], al[2][4];                                          \
            _Pragma("unroll")                                                     \
            for (int m = 0; m < 2; m++) {                                         \
                const int rm = mw * 32 + m * 16 + gid;                            \
                ah[m][0] = Ahu[ rm      * (GKP/2) + kw];                          \
                ah[m][1] = Ahu[(rm + 8) * (GKP/2) + kw];                          \
                ah[m][2] = Ahu[ rm      * (GKP/2) + kw + 4];                      \
                ah[m][3] = Ahu[(rm + 8) * (GKP/2) + kw + 4];                      \
                al[m][0] = Alu[ rm      * (GKP/2) + kw];                          \
                al[m][1] = Alu[(rm + 8) * (GKP/2) + kw];                          \
                al[m][2] = Alu[ rm      * (GKP/2) + kw + 4];                      \
                al[m][3] = Alu[(rm + 8) * (GKP/2) + kw + 4];                      \
            }                                                                     \
            _Pragma("unroll")                                                     \
            for (int n = 0; n < 8; n++) {                                         \
                const int cn = (cB0 + n * 8 + gid) * (GKP/2) + kw;                \
                uint32_t bh0 = Bhu[cn], bh1 = Bhu[cn + 4];                        \
                uint32_t bl0 = Blu[cn], bl1 = Blu[cn + 4];                        \
                mma_bf16(acc[0][n], ah[0][0], ah[0][1], ah[0][2], ah[0][3], bh0, bh1); \
                mma_bf16(acc[1][n], ah[1][0], ah[1][1], ah[1][2], ah[1][3], bh0, bh1); \
                mma_bf16(acc[0][n], ah[0][0], ah[0][1], ah[0][2], ah[0][3], bl0, bl1); \
                mma_bf16(acc[1][n], ah[1][0], ah[1][1], ah[1][2], ah[1][3], bl0, bl1); \
                mma_bf16(acc[0][n], al[0][0], al[0][1], al[0][2], al[0][3], bh0, bh1); \
                mma_bf16(acc[1][n], al[1][0], al[1][1], al[1][2], al[1][3], bh0, bh1); \
            }                                                                     \
        }                                                                         \
        __syncthreads();                                                          \
    }

// fused QKV projection: A = pre-split x, B = concatenated QKV weights.
__global__ __launch_bounds__(256) void gemm_qkv()
{
    const int row0 = blockIdx.y * 128, col0 = blockIdx.x * 128;
    GEMM_CORE(g_Xh, g_Xl, g_Wch, g_Wcl)

    float* dst; int nd, cofs;
    if (col0 < C_)              { dst = g_Q; nd = C_;   cofs = 0; }
    else if (col0 < C_ + KVC_)  { dst = g_K; nd = KVC_; cofs = C_; }
    else                        { dst = g_V; nd = KVC_; cofs = C_ + KVC_; }

#pragma unroll
    for (int m = 0; m < 2; m++) {
        const int row = row0 + mw * 32 + m * 16 + gid;
#pragma unroll
        for (int n = 0; n < 8; n++) {
            const int col = col0 + cB0 + n * 8 + 2 * tig;
            const float b0 = g_bcat[col], b1 = g_bcat[col + 1];
            const int cc = col - cofs;
            *(float2*)&dst[(size_t)row * nd + cc] =
                make_float2(acc[m][n][0] + b0, acc[m][n][1] + b1);
            *(float2*)&dst[(size_t)(row + 8) * nd + cc] =
                make_float2(acc[m][n][2] + b0, acc[m][n][3] + b1);
        }
    }
}

// output projection: A = pre-split Y, B = Wo.
__global__ __launch_bounds__(256) void gemm_o(const float* __restrict__ bias,
                                              float* __restrict__ out)
{
    const int row0 = blockIdx.y * 128, col0 = blockIdx.x * 128;
    GEMM_CORE(g_Yh, g_Yl, g_Woh, g_Wol)

#pragma unroll
    for (int m = 0; m < 2; m++) {
        const int row = row0 + mw * 32 + m * 16 + gid;
#pragma unroll
        for (int n = 0; n < 8; n++) {
            const int col = col0 + cB0 + n * 8 + 2 * tig;
            const float b0 = bias[col], b1 = bias[col + 1];
            *(float2*)&out[(size_t)row * C_ + col] =
                make_float2(acc[m][n][0] + b0, acc[m][n][1] + b1);
            *(float2*)&out[(size_t)(row + 8) * C_ + col] =
                make_float2(acc[m][n][2] + b0, acc[m][n][3] + b1);
        }
    }
}

// ---------------- attention pass 1 (mma): row max + sumexp ----------------
__global__ __launch_bounds__(256) void attn_stats_mma()
{
    __shared__ float Qs[64 * PAD];
    __shared__ float Ks[64 * PAD];
    __shared__ float redM[2][64];
    __shared__ float redL[2][64];

    const int tid  = threadIdx.x;
    const int w    = tid >> 5;
    const int lane = tid & 31;
    const int gid  = lane >> 2;
    const int tig  = lane & 3;
    const int mstrip = w & 3;
    const int nhalf  = w >> 2;
    const int row0  = mstrip * 16 + gid;
    const int nbase = nhalf * 32;

    const int bh = blockIdx.y;
    const int b  = bh >> 4, hq = bh & 15, h = hq >> 2;
    const int q0 = blockIdx.x * 64;

    {
        const float* src = &g_Q[(size_t)(b * T_ + q0) * C_ + hq * D_];
        for (int idx = tid; idx < 1024; idx += 256) {
            int r = idx >> 4, d = (idx & 15) << 2;
            float4 v = *(const float4*)&src[(size_t)r * C_ + d];
            v.x = tf32rn(v.x); v.y = tf32rn(v.y); v.z = tf32rn(v.z); v.w = tf32rn(v.w);
            *(float4*)&Qs[r * PAD + d] = v;
        }
    }

    float runm0 = -1e30f, runs0 = 0.f, runm1 = -1e30f, runs1 = 0.f;
    const int diag = q0 >> 6;

    for (int kt = 0; kt <= diag; kt++) {
        const int k0 = kt * 64;
        const float* ksrc = &g_K[(size_t)(b * T_ + k0) * KVC_ + h * D_];
        for (int idx = tid; idx < 1024; idx += 256) {
            int r = idx >> 4, d = (idx & 15) << 2;
            float4 v = *(const float4*)&ksrc[(size_t)r * KVC_ + d];
            v.x = tf32rn(v.x); v.y = tf32rn(v.y); v.z = tf32rn(v.z); v.w = tf32rn(v.w);
            *(float4*)&Ks[r * PAD + d] = v;
        }
        __syncthreads();

        float c[4][4];
#pragma unroll
        for (int nt = 0; nt < 4; nt++)
#pragma unroll
            for (int e = 0; e < 4; e++) c[nt][e] = 0.f;

#pragma unroll
        for (int ks2 = 0; ks2 < 8; ks2++) {
            const int d0 = ks2 * 8;
            uint32_t a0 = __float_as_uint(Qs[(row0    ) * PAD + d0 + tig]);
            uint32_t a1 = __float_as_uint(Qs[(row0 + 8) * PAD + d0 + tig]);
            uint32_t a2 = __float_as_uint(Qs[(row0    ) * PAD + d0 + tig + 4]);
            uint32_t a3 = __float_as_uint(Qs[(row0 + 8) * PAD + d0 + tig + 4]);
#pragma unroll
            for (int nt = 0; nt < 4; nt++) {
                const int nc = nbase + nt * 8 + gid;
                uint32_t b0 = __float_as_uint(Ks[nc * PAD + d0 + tig]);
                uint32_t b1 = __float_as_uint(Ks[nc * PAD + d0 + tig + 4]);
                mma_tf32(c[nt], a0, a1, a2, a3, b0, b1);
            }
        }

        const bool dm = (kt == diag);
#pragma unroll
        for (int nt = 0; nt < 4; nt++) {
            const int colb = k0 + nbase + nt * 8 + 2 * tig;
#pragma unroll
            for (int e = 0; e < 2; e++) {
                float v0 = c[nt][e]     * 0.125f;
                float v1 = c[nt][2 + e] * 0.125f;
                if (dm && colb + e > q0 + row0    ) v0 = -1e30f;
                if (dm && colb + e > q0 + row0 + 8) v1 = -1e30f;
                c[nt][e] = v0; c[nt][2 + e] = v1;
            }
        }

        float m0 = c[0][0], m1 = c[0][2];
#pragma unroll
        for (int nt = 0; nt < 4; nt++) {
            m0 = fmaxf(m0, fmaxf(c[nt][0], c[nt][1]));
            m1 = fmaxf(m1, fmaxf(c[nt][2], c[nt][3]));
        }
        m0 = fmaxf(m0, __shfl_xor_sync(0xffffffffu, m0, 1));
        m0 = fmaxf(m0, __shfl_xor_sync(0xffffffffu, m0, 2));
        m1 = fmaxf(m1, __shfl_xor_sync(0xffffffffu, m1, 1));
        m1 = fmaxf(m1, __shfl_xor_sync(0xffffffffu, m1, 2));

        const float nm0 = fmaxf(runm0, m0);
        const float nm1 = fmaxf(runm1, m1);
        float s0 = 0.f, s1 = 0.f;
#pragma unroll
        for (int nt = 0; nt < 4; nt++) {
            s0 += __expf(c[nt][0] - nm0) + __expf(c[nt][1] - nm0);
            s1 += __expf(c[nt][2] - nm1) + __expf(c[nt][3] - nm1);
        }
        s0 += __shfl_xor_sync(0xffffffffu, s0, 1);
        s0 += __shfl_xor_sync(0xffffffffu, s0, 2);
        s1 += __shfl_xor_sync(0xffffffffu, s1, 1);
        s1 += __shfl_xor_sync(0xffffffffu, s1, 2);

        runs0 = runs0 * __expf(runm0 - nm0) + s0;  runm0 = nm0;
        runs1 = runs1 * __expf(runm1 - nm1) + s1;  runm1 = nm1;
        __syncthreads();
    }

    if (tig == 0) {
        redM[nhalf][row0]     = runm0;  redL[nhalf][row0]     = runs0;
        redM[nhalf][row0 + 8] = runm1;  redL[nhalf][row0 + 8] = runs1;
    }
    __syncthreads();
    if (nhalf == 0 && tig == 0) {
#pragma unroll
        for (int rr = 0; rr < 2; rr++) {
            const int r = row0 + rr * 8;
            const float ma = redM[0][r], mb = redM[1][r];
            const float m  = fmaxf(ma, mb);
            const float l  = redL[0][r] * __expf(ma - m) + redL[1][r] * __expf(mb - m);
            g_M[bh * T_ + q0 + r] = m;
            g_L[bh * T_ + q0 + r] = l;
        }
    }
}

// ---------------- attention pass 2: 128-row Q tiles, 512 threads ----------------
__global__ __launch_bounds__(512) void attn_finalize_mma(float* __restrict__ att,
                                                         int write_att)
{
    extern __shared__ float smdyn[];
    float* Qs = smdyn;                       // 128 x PAD
    float* Ks = smdyn + 128 * PAD;           // 64 x PAD
    float* Vs = smdyn + 192 * PAD;           // 64 x PAD
    float* Ps = smdyn + 256 * PAD;           // 128 x PAD

    const int tid  = threadIdx.x;
    const int w    = tid >> 5;
    const int lane = tid & 31;
    const int gid  = lane >> 2;
    const int tig  = lane & 3;
    const int mstrip = w & 7;                // 8 strips of 16 rows
    const int nhalf  = w >> 3;               // 2 halves of 32 cols
    const int row0  = mstrip * 16 + gid;     // 0..127 (+8)
    const int nbase = nhalf * 32;

    const int bh = blockIdx.y;
    const int b  = bh >> 4, hq = bh & 15, h = hq >> 2, g = hq & 3;
    const int bx = blockIdx.x;
    const int q0 = bx * 128;
    const size_t attbase = (size_t)((b * G_ + g) * HKV_ + h) * T_ * T_;

    {
        const float* src = &g_Q[(size_t)(b * T_ + q0) * C_ + hq * D_];
        for (int idx = tid; idx < 2048; idx += 512) {
            int r = idx >> 4, d = (idx & 15) << 2;
            float4 v = *(const float4*)&src[(size_t)r * C_ + d];
            v.x = tf32rn(v.x); v.y = tf32rn(v.y); v.z = tf32rn(v.z); v.w = tf32rn(v.w);
            *(float4*)&Qs[r * PAD + d] = v;
        }
    }

    const float mr0 = g_M[bh * T_ + q0 + row0];
    const float li0 = 1.f / g_L[bh * T_ + q0 + row0];
    const float mr1 = g_M[bh * T_ + q0 + row0 + 8];
    const float li1 = 1.f / g_L[bh * T_ + q0 + row0 + 8];

    float yc[4][4];
#pragma unroll
    for (int nt = 0; nt < 4; nt++)
#pragma unroll
        for (int e = 0; e < 4; e++) yc[nt][e] = 0.f;

    const int ktlast = 2 * bx + 1;           // last kt with any unmasked element
    for (int kt = 0; kt < T_ / 64; kt++) {
        const int k0 = kt * 64;
        if (kt > ktlast) {
            if (write_att) {
                const float4 z = make_float4(0.f, 0.f, 0.f, 0.f);
                for (int idx = tid; idx < 2048; idx += 512) {
                    int r = idx >> 4, cc = (idx & 15) << 2;
                    *(float4*)&att[attbase + (size_t)(q0 + r) * T_ + k0 + cc] = z;
                }
            }
            continue;
        }

        {
            const float* ksrc = &g_K[(size_t)(b * T_ + k0) * KVC_ + h * D_];
            const float* vsrc = &g_V[(size_t)(b * T_ + k0) * KVC_ + h * D_];
            for (int idx = tid; idx < 1024; idx += 512) {
                int r = idx >> 4, d = (idx & 15) << 2;
                float4 kv = *(const float4*)&ksrc[(size_t)r * KVC_ + d];
                float4 vv = *(const float4*)&vsrc[(size_t)r * KVC_ + d];
                kv.x = tf32rn(kv.x); kv.y = tf32rn(kv.y); kv.z = tf32rn(kv.z); kv.w = tf32rn(kv.w);
                vv.x = tf32rn(vv.x); vv.y = tf32rn(vv.y); vv.z = tf32rn(vv.z); vv.w = tf32rn(vv.w);
                *(float4*)&Ks[r * PAD + d] = kv;
                *(float4*)&Vs[r * PAD + d] = vv;
            }
        }
        __syncthreads();

        float c[4][4];
#pragma unroll
        for (int nt = 0; nt < 4; nt++)
#pragma unroll
            for (int e = 0; e < 4; e++) c[nt][e] = 0.f;
#pragma unroll
        for (int ks2 = 0; ks2 < 8; ks2++) {
            const int d0 = ks2 * 8;
            uint32_t a0 = __float_as_uint(Qs[(row0    ) * PAD + d0 + tig]);
            uint32_t a1 = __float_as_uint(Qs[(row0 + 8) * PAD + d0 + tig]);
            uint32_t a2 = __float_as_uint(Qs[(row0    ) * PAD + d0 + tig + 4]);
            uint32_t a3 = __float_as_uint(Qs[(row0 + 8) * PAD + d0 + tig + 4]);
#pragma unroll
            for (int nt = 0; nt < 4; nt++) {
                const int nc = nbase + nt * 8 + gid;
                uint32_t b0 = __float_as_uint(Ks[nc * PAD + d0 + tig]);
                uint32_t b1 = __float_as_uint(Ks[nc * PAD + d0 + tig + 4]);
                mma_tf32(c[nt], a0, a1, a2, a3, b0, b1);
            }
        }

        const bool dm = (kt >= 2 * bx);      // any masking possible in this tile
#pragma unroll
        for (int nt = 0; nt < 4; nt++) {
            const int col  = nbase + nt * 8 + 2 * tig;
            const int colg = k0 + col;
            float v00 = c[nt][0] * 0.125f, v01 = c[nt][1] * 0.125f;
            float v10 = c[nt][2] * 0.125f, v11 = c[nt][3] * 0.125f;
            if (dm) {
                if (colg     > q0 + row0    ) v00 = -1e30f;
                if (colg + 1 > q0 + row0    ) v01 = -1e30f;
                if (colg     > q0 + row0 + 8) v10 = -1e30f;
                if (colg + 1 > q0 + row0 + 8) v11 = -1e30f;
            }
            const float p00 = __expf(v00 - mr0) * li0;
            const float p01 = __expf(v01 - mr0) * li0;
            const float p10 = __expf(v10 - mr1) * li1;
            const float p11 = __expf(v11 - mr1) * li1;
            *(float2*)&Ps[(row0    ) * PAD + col] = make_float2(tf32rn(p00), tf32rn(p01));
            *(float2*)&Ps[(row0 + 8) * PAD + col] = make_float2(tf32rn(p10), tf32rn(p11));
            if (write_att) {
                *(float2*)&att[attbase + (size_t)(q0 + row0    ) * T_ + colg] = make_float2(p00, p01);
                *(float2*)&att[attbase + (size_t)(q0 + row0 + 8) * T_ + colg] = make_float2(p10, p11);
            }
        }
        __syncthreads();

#pragma unroll
        for (int ks2 = 0; ks2 < 8; ks2++) {
            const int kc0 = ks2 * 8;
            uint32_t a0 = __float_as_uint(Ps[(row0    ) * PAD + kc0 + tig]);
            uint32_t a1 = __float_as_uint(Ps[(row0 + 8) * PAD + kc0 + tig]);
            uint32_t a2 = __float_as_uint(Ps[(row0    ) * PAD + kc0 + tig + 4]);
            uint32_t a3 = __float_as_uint(Ps[(row0 + 8) * PAD + kc0 + tig + 4]);
#pragma unroll
            for (int nt = 0; nt < 4; nt++) {
                const int dc = nbase + nt * 8 + gid;
                uint32_t b0 = __float_as_uint(Vs[(kc0 + tig    ) * PAD + dc]);
                uint32_t b1 = __float_as_uint(Vs[(kc0 + tig + 4) * PAD + dc]);
                mma_tf32(yc[nt], a0, a1, a2, a3, b0, b1);
            }
        }
        __syncthreads();
    }

    // write Y as pre-split bf16 hi/lo (feeds gemm_o directly)
    uint32_t* yhu = (uint32_t*)g_Yh;
    uint32_t* ylu = (uint32_t*)g_Yl;
#pragma unroll
    for (int nt = 0; nt < 4; nt++) {
        const int col = nbase + nt * 8 + 2 * tig;
        const size_t i0 = ((size_t)(b * T_ + q0 + row0    ) * C_ + hq * D_ + col) >> 1;
        const size_t i1 = ((size_t)(b * T_ + q0 + row0 + 8) * C_ + hq * D_ + col) >> 1;
        float h00 = __bfloat162float(__float2bfloat16_rn(yc[nt][0]));
        float h01 = __bfloat162float(__float2bfloat16_rn(yc[nt][1]));
        float h10 = __bfloat162float(__float2bfloat16_rn(yc[nt][2]));
        float h11 = __bfloat162float(__float2bfloat16_rn(yc[nt][3]));
        yhu[i0] = pack_bf2(h00, h01);
        ylu[i0] = pack_bf2(yc[nt][0] - h00, yc[nt][1] - h01);
        yhu[i1] = pack_bf2(h10, h11);
        ylu[i1] = pack_bf2(yc[nt][2] - h10, yc[nt][3] - h11);
    }
}

// ---------------- launch ----------------
#define FIN_SMEM (384 * PAD * (int)sizeof(float))   // 104,448 B

extern "C" void kernel_launch(void* const* d_in, const int* in_sizes, int n_in,
                              void* d_out, int out_size)
{
    const float* x  = (const float*)d_in[0];
    const float* Wq = (const float*)d_in[1];
    const float* bq = (const float*)d_in[2];
    const float* Wk = (const float*)d_in[3];
    const float* bk = (const float*)d_in[4];
    const float* Wv = (const float*)d_in[5];
    const float* bv = (const float*)d_in[6];
    const float* Wo = (const float*)d_in[7];
    const float* bo = (const float*)d_in[8];

    static float *qp = nullptr, *bcat = nullptr;
    static __nv_bfloat16 *xh, *xl, *wch, *wcl, *woh, *wol;
    if (!qp) {
        cudaGetSymbolAddress((void**)&qp,   g_Q);
        cudaGetSymbolAddress((void**)&bcat, g_bcat);
        cudaGetSymbolAddress((void**)&xh,   g_Xh);
        cudaGetSymbolAddress((void**)&xl,   g_Xl);
        cudaGetSymbolAddress((void**)&wch,  g_Wch);
        cudaGetSymbolAddress((void**)&wcl,  g_Wcl);
        cudaGetSymbolAddress((void**)&woh,  g_Woh);
        cudaGetSymbolAddress((void**)&wol,  g_Wol);
        cudaFuncSetAttribute(attn_finalize_mma,
                             cudaFuncAttributeMaxDynamicSharedMemorySize, FIN_SMEM);
    }

    const size_t yElems   = (size_t)N_ * C_;
    const size_t attElems = (size_t)B_ * G_ * HKV_ * T_ * T_;
    float* out = (float*)d_out;
    float* yOut;
    float* attOut;
    int    writeAtt;
    size_t osz = (size_t)out_size;
    if (osz >= yElems + attElems)      { yOut = out; attOut = out + yElems; writeAtt = 1; }
    else if (osz == attElems)          { yOut = qp;  attOut = out;          writeAtt = 1; }
    else                               { yOut = out; attOut = qp;           writeAtt = 0; }

    // bias concat (async D2D copies are graph-capturable)
    cudaMemcpyAsync(bcat,             bq, C_   * sizeof(float), cudaMemcpyDeviceToDevice);
    cudaMemcpyAsync(bcat + C_,        bk, KVC_ * sizeof(float), cudaMemcpyDeviceToDevice);
    cudaMemcpyAsync(bcat + C_ + KVC_, bv, KVC_ * sizeof(float), cudaMemcpyDeviceToDevice);

    dim3 blk(256);
    dim3 tb(32, 8);
    split_x<<<(N_ * C_ / 4) / 256, blk>>>(x, xh, xl);
    transpose_split<<<dim3(C_   / 32, C_ / 32), tb>>>(Wq, wch,                          wcl,                          C_, C_);
    transpose_split<<<dim3(KVC_ / 32, C_ / 32), tb>>>(Wk, wch + (size_t)C_ * C_,        wcl + (size_t)C_ * C_,        C_, KVC_);
    transpose_split<<<dim3(KVC_ / 32, C_ / 32), tb>>>(Wv, wch + (size_t)(C_+KVC_) * C_, wcl + (size_t)(C_+KVC_) * C_, C_, KVC_);
    transpose_split<<<dim3(C_   / 32, C_ / 32), tb>>>(Wo, woh, wol, C_, C_);

    gemm_qkv<<<dim3(QKV_ / 128, N_ / 128), blk>>>();

    attn_stats_mma   <<<dim3(T_ / 64,  B_ * HQ_), blk>>>();
    attn_finalize_mma<<<dim3(T_ / 128, B_ * HQ_), dim3(512), FIN_SMEM>>>(attOut, writeAtt);

    gemm_o<<<dim3(C_ / 128, N_ / 128), blk>>>(bo, yOut);
}

// round 14
// speedup vs baseline: 1.0618x; 1.0618x over previous
// R14 = R12 resubmitted unchanged (3rd attempt): R12/R13 died at GPU
// acquisition (broker pool saturated; failure precedes compilation). The R12
// change-set (cp.async double-buffered GEMM, finalize reverted to
// 64-row/69KB/3-CTA-per-SM, tf32 rounding moved to QKV epilogue) remains
// unmeasured; holding it stable for clean attribution.
#include <cuda_runtime.h>
#include <cuda_bf16.h>
#include <math.h>
#include <stdint.h>

#define B_   4
#define T_   2048
#define C_   1024
#define HQ_  16
#define HKV_ 4
#define D_   64
#define G_   4
#define N_   (B_*T_)        // 8192 rows
#define KVC_ (HKV_*D_)      // 256
#define QKV_ (C_+2*KVC_)    // 1536 concatenated proj cols
#define PAD  68             // attention smem row stride (floats)
#define GKP  40             // gemm smem row stride in bf16 elems

// ---------------- scratch (no allocations allowed) ----------------
__device__ float g_Q[(size_t)N_*C_];     // tf32-rounded at producer
__device__ float g_K[(size_t)N_*KVC_];   // tf32-rounded at producer
__device__ float g_V[(size_t)N_*KVC_];   // tf32-rounded at producer
__device__ float g_M[B_*HQ_*T_];
__device__ float g_L[B_*HQ_*T_];
__device__ float g_bcat[QKV_];
__device__ __nv_bfloat16 g_Xh[(size_t)N_*C_], g_Xl[(size_t)N_*C_];
__device__ __nv_bfloat16 g_Yh[(size_t)N_*C_], g_Yl[(size_t)N_*C_];
__device__ __nv_bfloat16 g_Wch[(size_t)QKV_*C_], g_Wcl[(size_t)QKV_*C_];
__device__ __nv_bfloat16 g_Woh[(size_t)C_*C_],   g_Wol[(size_t)C_*C_];

// ---------------- helpers ----------------
__device__ __forceinline__ void mma_tf32(float c[4],
    uint32_t a0, uint32_t a1, uint32_t a2, uint32_t a3,
    uint32_t b0, uint32_t b1)
{
    asm volatile(
        "mma.sync.aligned.m16n8k8.row.col.f32.tf32.tf32.f32 "
        "{%0,%1,%2,%3}, {%4,%5,%6,%7}, {%8,%9}, {%0,%1,%2,%3};\n"
        : "+f"(c[0]), "+f"(c[1]), "+f"(c[2]), "+f"(c[3])
        : "r"(a0), "r"(a1), "r"(a2), "r"(a3), "r"(b0), "r"(b1));
}
__device__ __forceinline__ void mma_bf16(float c[4],
    uint32_t a0, uint32_t a1, uint32_t a2, uint32_t a3,
    uint32_t b0, uint32_t b1)
{
    asm volatile(
        "mma.sync.aligned.m16n8k16.row.col.f32.bf16.bf16.f32 "
        "{%0,%1,%2,%3}, {%4,%5,%6,%7}, {%8,%9}, {%0,%1,%2,%3};\n"
        : "+f"(c[0]), "+f"(c[1]), "+f"(c[2]), "+f"(c[3])
        : "r"(a0), "r"(a1), "r"(a2), "r"(a3), "r"(b0), "r"(b1));
}
__device__ __forceinline__ float tf32rn(float x)
{
    uint32_t u;
    asm("cvt.rna.tf32.f32 %0, %1;" : "=r"(u) : "f"(x));
    return __uint_as_float(u);
}
__device__ __forceinline__ uint32_t pack_bf2(float x, float y)
{
    __nv_bfloat162 t = __floats2bfloat162_rn(x, y);
    return *(uint32_t*)&t;
}
__device__ __forceinline__ void cp16(void* smem_dst, const void* gmem_src)
{
    uint32_t s = (uint32_t)__cvta_generic_to_shared(smem_dst);
    asm volatile("cp.async.cg.shared.global [%0], [%1], 16;\n" :: "r"(s), "l"(gmem_src));
}
#define CP_COMMIT()  asm volatile("cp.async.commit_group;\n" ::: "memory")
#define CP_WAIT(n)   asm volatile("cp.async.wait_group %0;\n" :: "n"(n) : "memory")

// ---------------- x -> bf16 hi/lo split ----------------
__global__ __launch_bounds__(256) void split_x(const float* __restrict__ X,
                                               __nv_bfloat16* __restrict__ Xh,
                                               __nv_bfloat16* __restrict__ Xl)
{
    const int idx = blockIdx.x * 256 + threadIdx.x;
    float4 v = ((const float4*)X)[idx];
    float hx = __bfloat162float(__float2bfloat16_rn(v.x));
    float hy = __bfloat162float(__float2bfloat16_rn(v.y));
    float hz = __bfloat162float(__float2bfloat16_rn(v.z));
    float hw = __bfloat162float(__float2bfloat16_rn(v.w));
    ((uint2*)Xh)[idx] = make_uint2(pack_bf2(hx, hy), pack_bf2(hz, hw));
    ((uint2*)Xl)[idx] = make_uint2(pack_bf2(v.x - hx, v.y - hy), pack_bf2(v.z - hz, v.w - hw));
}

// ---------------- weight prep: transpose + bf16 hi/lo split ----------------
__global__ void transpose_split(const float* __restrict__ W,
                                __nv_bfloat16* __restrict__ Th,
                                __nv_bfloat16* __restrict__ Tl,
                                int K, int N)
{
    __shared__ float s[32][33];
    const int n0 = blockIdx.x * 32, k0 = blockIdx.y * 32;
    const int tx = threadIdx.x, ty = threadIdx.y;
#pragma unroll
    for (int i = 0; i < 32; i += 8)
        s[ty + i][tx] = W[(size_t)(k0 + ty + i) * N + n0 + tx];
    __syncthreads();
#pragma unroll
    for (int i = 0; i < 32; i += 8) {
        float v = s[tx][ty + i];
        __nv_bfloat16 h = __float2bfloat16_rn(v);
        __nv_bfloat16 l = __float2bfloat16_rn(v - __bfloat162float(h));
        Th[(size_t)(n0 + ty + i) * K + k0 + tx] = h;
        Tl[(size_t)(n0 + ty + i) * K + k0 + tx] = l;
    }
}

// ---------------- cp.async double-buffered bf16x3 GEMM mainloop ----------------
// 128x128x32 tile, 2-stage pipeline, 256 thr, acc[2][8][4]. K = 1024 fixed.
// Dynamic smem: 2 stages x 4 arrays x 128*GKP bf16 = 81,920 B.
#define GEMM_SMEM (2 * 4 * 128 * GKP * (int)sizeof(__nv_bfloat16))

#define GEMM_CORE(Ath, Atl, Bth, Btl)                                             \
    extern __shared__ __nv_bfloat16 smg[];                                        \
    const int SS = 128 * GKP;                                                     \
    __nv_bfloat16 *Ahb = smg,          *Alb = smg + 2 * SS;                       \
    __nv_bfloat16 *Bhb = smg + 4 * SS, *Blb = smg + 6 * SS;                       \
    const int tid  = threadIdx.x;                                                 \
    const int w    = tid >> 5;                                                    \
    const int lane = tid & 31;                                                    \
    const int gid  = lane >> 2;                                                   \
    const int tig  = lane & 3;                                                    \
    const int mw   = w & 3;                                                       \
    const int nw   = w >> 2;                                                      \
    const int cB0  = nw * 64;                                                     \
    auto pref = [&](int st, int kbase) {                                          \
        _Pragma("unroll")                                                         \
        for (int i = 0; i < 2; i++) {                                             \
            int idx8 = tid + i * 256;                                             \
            int r = idx8 >> 2, k8 = (idx8 & 3) << 3;                              \
            int so = st * SS + r * GKP + k8;                                      \
            cp16(&Ahb[so], &Ath[(size_t)(row0 + r) * 1024 + kbase + k8]);         \
            cp16(&Alb[so], &Atl[(size_t)(row0 + r) * 1024 + kbase + k8]);         \
            cp16(&Bhb[so], &Bth[(size_t)(col0 + r) * 1024 + kbase + k8]);         \
            cp16(&Blb[so], &Btl[(size_t)(col0 + r) * 1024 + kbase + k8]);         \
        }                                                                         \
    };                                                                            \
    float acc[2][8][4];                                                           \
    _Pragma("unroll")                                                             \
    for (int m = 0; m < 2; m++)                                                   \
        _Pragma("unroll")                                                         \
        for (int n = 0; n < 8; n++)                                               \
            _Pragma("unroll")                                                     \
            for (int e = 0; e < 4; e++) acc[m][n][e] = 0.f;                       \
    pref(0, 0);                                                                   \
    CP_COMMIT();                                                                  \
    for (int it = 0; it < 32; it++) {                                             \
        if (it + 1 < 32) { pref((it + 1) & 1, (it + 1) * 32); CP_COMMIT(); }      \
        if (it + 1 < 32) CP_WAIT(1); else CP_WAIT(0);                             \
        __syncthreads();                                                          \
        const int st = it & 1;                                                    \
        uint32_t* Ahu = (uint32_t*)(Ahb + st * SS);                               \
        uint32_t* Alu = (uint32_t*)(Alb + st * SS);                               \
        uint32_t* Bhu = (uint32_t*)(Bhb + st * SS);                               \
        uint32_t* Blu = (uint32_t*)(Blb + st * SS);                               \
        _Pragma("unroll")                                                         \
        for (int kk = 0; kk < 32; kk += 16) {                                     \
            const int kw = (kk >> 1) + tig;                                       \
            uint32_t ah[2][4], al[2][4];                                          \
            _Pragma("unroll")                                                     \
            for (int m = 0; m < 2; m++) {                                         \
                const int rm = mw * 32 + m * 16 + gid;                            \
                ah[m][0] = Ahu[ rm      * (GKP/2) + kw];                          \
                ah[m][1] = Ahu[(rm + 8) * (GKP/2) + kw];                          \
                ah[m][2] = Ahu[ rm      * (GKP/2) + kw + 4];                      \
                ah[m][3] = Ahu[(rm + 8) * (GKP/2) + kw + 4];                      \
                al[m][0] = Alu[ rm      * (GKP/2) + kw];                          \
                al[m][1] = Alu[(rm + 8) * (GKP/2) + kw];                          \
                al[m][2] = Alu[ rm      * (GKP/2) + kw + 4];                      \
                al[m][3] = Alu[(rm + 8) * (GKP/2) + kw + 4];                      \
            }                                                                     \
            _Pragma("unroll")                                                     \
            for (int n = 0; n < 8; n++) {                                         \
                const int cn = (cB0 + n * 8 + gid) * (GKP/2) + kw;                \
                uint32_t bh0 = Bhu[cn], bh1 = Bhu[cn + 4];                        \
                uint32_t bl0 = Blu[cn], bl1 = Blu[cn + 4];                        \
                mma_bf16(acc[0][n], ah[0][0], ah[0][1], ah[0][2], ah[0][3], bh0, bh1); \
                mma_bf16(acc[1][n], ah[1][0], ah[1][1], ah[1][2], ah[1][3], bh0, bh1); \
                mma_bf16(acc[0][n], ah[0][0], ah[0][1], ah[0][2], ah[0][3], bl0, bl1); \
                mma_bf16(acc[1][n], ah[1][0], ah[1][1], ah[1][2], ah[1][3], bl0, bl1); \
                mma_bf16(acc[0][n], al[0][0], al[0][1], al[0][2], al[0][3], bh0, bh1); \
                mma_bf16(acc[1][n], al[1][0], al[1][1], al[1][2], al[1][3], bh0, bh1); \
            }                                                                     \
        }                                                                         \
        __syncthreads();                                                          \
    }

// fused QKV projection; epilogue tf32-rounds (attention consumed rounded values anyway)
__global__ __launch_bounds__(256) void gemm_qkv()
{
    const int row0 = blockIdx.y * 128, col0 = blockIdx.x * 128;
    GEMM_CORE(g_Xh, g_Xl, g_Wch, g_Wcl)

    float* dst; int nd, cofs;
    if (col0 < C_)              { dst = g_Q; nd = C_;   cofs = 0; }
    else if (col0 < C_ + KVC_)  { dst = g_K; nd = KVC_; cofs = C_; }
    else                        { dst = g_V; nd = KVC_; cofs = C_ + KVC_; }

#pragma unroll
    for (int m = 0; m < 2; m++) {
        const int row = row0 + mw * 32 + m * 16 + gid;
#pragma unroll
        for (int n = 0; n < 8; n++) {
            const int col = col0 + cB0 + n * 8 + 2 * tig;
            const float b0 = g_bcat[col], b1 = g_bcat[col + 1];
            const int cc = col - cofs;
            *(float2*)&dst[(size_t)row * nd + cc] =
                make_float2(tf32rn(acc[m][n][0] + b0), tf32rn(acc[m][n][1] + b1));
            *(float2*)&dst[(size_t)(row + 8) * nd + cc] =
                make_float2(tf32rn(acc[m][n][2] + b0), tf32rn(acc[m][n][3] + b1));
        }
    }
}

// output projection
__global__ __launch_bounds__(256) void gemm_o(const float* __restrict__ bias,
                                              float* __restrict__ out)
{
    const int row0 = blockIdx.y * 128, col0 = blockIdx.x * 128;
    GEMM_CORE(g_Yh, g_Yl, g_Woh, g_Wol)

#pragma unroll
    for (int m = 0; m < 2; m++) {
        const int row = row0 + mw * 32 + m * 16 + gid;
#pragma unroll
        for (int n = 0; n < 8; n++) {
            const int col = col0 + cB0 + n * 8 + 2 * tig;
            const float b0 = bias[col], b1 = bias[col + 1];
            *(float2*)&out[(size_t)row * C_ + col] =
                make_float2(acc[m][n][0] + b0, acc[m][n][1] + b1);
            *(float2*)&out[(size_t)(row + 8) * C_ + col] =
                make_float2(acc[m][n][2] + b0, acc[m][n][3] + b1);
        }
    }
}

// ---------------- attention pass 1: row max + sumexp (inputs pre-rounded) ----------------
__global__ __launch_bounds__(256) void attn_stats_mma()
{
    __shared__ float Qs[64 * PAD];
    __shared__ float Ks[64 * PAD];
    __shared__ float redM[2][64];
    __shared__ float redL[2][64];

    const int tid  = threadIdx.x;
    const int w    = tid >> 5;
    const int lane = tid & 31;
    const int gid  = lane >> 2;
    const int tig  = lane & 3;
    const int mstrip = w & 3;
    const int nhalf  = w >> 2;
    const int row0  = mstrip * 16 + gid;
    const int nbase = nhalf * 32;

    const int bh = blockIdx.y;
    const int b  = bh >> 4, hq = bh & 15, h = hq >> 2;
    const int q0 = blockIdx.x * 64;

    {
        const float* src = &g_Q[(size_t)(b * T_ + q0) * C_ + hq * D_];
        for (int idx = tid; idx < 1024; idx += 256) {
            int r = idx >> 4, d = (idx & 15) << 2;
            *(float4*)&Qs[r * PAD + d] = *(const float4*)&src[(size_t)r * C_ + d];
        }
    }

    float runm0 = -1e30f, runs0 = 0.f, runm1 = -1e30f, runs1 = 0.f;
    const int diag = q0 >> 6;

    for (int kt = 0; kt <= diag; kt++) {
        const int k0 = kt * 64;
        const float* ksrc = &g_K[(size_t)(b * T_ + k0) * KVC_ + h * D_];
        for (int idx = tid; idx < 1024; idx += 256) {
            int r = idx >> 4, d = (idx & 15) << 2;
            *(float4*)&Ks[r * PAD + d] = *(const float4*)&ksrc[(size_t)r * KVC_ + d];
        }
        __syncthreads();

        float c[4][4];
#pragma unroll
        for (int nt = 0; nt < 4; nt++)
#pragma unroll
            for (int e = 0; e < 4; e++) c[nt][e] = 0.f;

#pragma unroll
        for (int ks2 = 0; ks2 < 8; ks2++) {
            const int d0 = ks2 * 8;
            uint32_t a0 = __float_as_uint(Qs[(row0    ) * PAD + d0 + tig]);
            uint32_t a1 = __float_as_uint(Qs[(row0 + 8) * PAD + d0 + tig]);
            uint32_t a2 = __float_as_uint(Qs[(row0    ) * PAD + d0 + tig + 4]);
            uint32_t a3 = __float_as_uint(Qs[(row0 + 8) * PAD + d0 + tig + 4]);
#pragma unroll
            for (int nt = 0; nt < 4; nt++) {
                const int nc = nbase + nt * 8 + gid;
                uint32_t b0 = __float_as_uint(Ks[nc * PAD + d0 + tig]);
                uint32_t b1 = __float_as_uint(Ks[nc * PAD + d0 + tig + 4]);
                mma_tf32(c[nt], a0, a1, a2, a3, b0, b1);
            }
        }

        const bool dm = (kt == diag);
#pragma unroll
        for (int nt = 0; nt < 4; nt++) {
            const int colb = k0 + nbase + nt * 8 + 2 * tig;
#pragma unroll
            for (int e = 0; e < 2; e++) {
                float v0 = c[nt][e]     * 0.125f;
                float v1 = c[nt][2 + e] * 0.125f;
                if (dm && colb + e > q0 + row0    ) v0 = -1e30f;
                if (dm && colb + e > q0 + row0 + 8) v1 = -1e30f;
                c[nt][e] = v0; c[nt][2 + e] = v1;
            }
        }

        float m0 = c[0][0], m1 = c[0][2];
#pragma unroll
        for (int nt = 0; nt < 4; nt++) {
            m0 = fmaxf(m0, fmaxf(c[nt][0], c[nt][1]));
            m1 = fmaxf(m1, fmaxf(c[nt][2], c[nt][3]));
        }
        m0 = fmaxf(m0, __shfl_xor_sync(0xffffffffu, m0, 1));
        m0 = fmaxf(m0, __shfl_xor_sync(0xffffffffu, m0, 2));
        m1 = fmaxf(m1, __shfl_xor_sync(0xffffffffu, m1, 1));
        m1 = fmaxf(m1, __shfl_xor_sync(0xffffffffu, m1, 2));

        const float nm0 = fmaxf(runm0, m0);
        const float nm1 = fmaxf(runm1, m1);
        float s0 = 0.f, s1 = 0.f;
#pragma unroll
        for (int nt = 0; nt < 4; nt++) {
            s0 += __expf(c[nt][0] - nm0) + __expf(c[nt][1] - nm0);
            s1 += __expf(c[nt][2] - nm1) + __expf(c[nt][3] - nm1);
        }
        s0 += __shfl_xor_sync(0xffffffffu, s0, 1);
        s0 += __shfl_xor_sync(0xffffffffu, s0, 2);
        s1 += __shfl_xor_sync(0xffffffffu, s1, 1);
        s1 += __shfl_xor_sync(0xffffffffu, s1, 2);

        runs0 = runs0 * __expf(runm0 - nm0) + s0;  runm0 = nm0;
        runs1 = runs1 * __expf(runm1 - nm1) + s1;  runm1 = nm1;
        __syncthreads();
    }

    if (tig == 0) {
        redM[nhalf][row0]     = runm0;  redL[nhalf][row0]     = runs0;
        redM[nhalf][row0 + 8] = runm1;  redL[nhalf][row0 + 8] = runs1;
    }
    __syncthreads();
    if (nhalf == 0 && tig == 0) {
#pragma unroll
        for (int rr = 0; rr < 2; rr++) {
            const int r = row0 + rr * 8;
            const float ma = redM[0][r], mb = redM[1][r];
            const float m  = fmaxf(ma, mb);
            const float l  = redL[0][r] * __expf(ma - m) + redL[1][r] * __expf(mb - m);
            g_M[bh * T_ + q0 + r] = m;
            g_L[bh * T_ + q0 + r] = l;
        }
    }
}

// ---------------- attention pass 2: 64-row tiles (3 CTA/SM), Y -> split bf16 ----------------
__global__ __launch_bounds__(256) void attn_finalize_mma(float* __restrict__ att,
                                                         int write_att)
{
    extern __shared__ float smdyn[];
    float* Qs = smdyn;
    float* Ks = smdyn + 64 * PAD;
    float* Vs = smdyn + 2 * 64 * PAD;
    float* Ps = smdyn + 3 * 64 * PAD;

    const int tid  = threadIdx.x;
    const int w    = tid >> 5;
    const int lane = tid & 31;
    const int gid  = lane >> 2;
    const int tig  = lane & 3;
    const int mstrip = w & 3;
    const int nhalf  = w >> 2;
    const int row0  = mstrip * 16 + gid;
    const int nbase = nhalf * 32;

    const int bh = blockIdx.y;
    const int b  = bh >> 4, hq = bh & 15, h = hq >> 2, g = hq & 3;
    const int q0 = blockIdx.x * 64;
    const size_t attbase = (size_t)((b * G_ + g) * HKV_ + h) * T_ * T_;

    {
        const float* src = &g_Q[(size_t)(b * T_ + q0) * C_ + hq * D_];
        for (int idx = tid; idx < 1024; idx += 256) {
            int r = idx >> 4, d = (idx & 15) << 2;
            *(float4*)&Qs[r * PAD + d] = *(const float4*)&src[(size_t)r * C_ + d];
        }
    }

    const float mr0 = g_M[bh * T_ + q0 + row0];
    const float li0 = 1.f / g_L[bh * T_ + q0 + row0];
    const float mr1 = g_M[bh * T_ + q0 + row0 + 8];
    const float li1 = 1.f / g_L[bh * T_ + q0 + row0 + 8];

    float yc[4][4];
#pragma unroll
    for (int nt = 0; nt < 4; nt++)
#pragma unroll
        for (int e = 0; e < 4; e++) yc[nt][e] = 0.f;

    const int diag = q0 >> 6;
    for (int kt = 0; kt < T_ / 64; kt++) {
        const int k0 = kt * 64;
        if (kt > diag) {
            if (write_att) {
                const float4 z = make_float4(0.f, 0.f, 0.f, 0.f);
                for (int idx = tid; idx < 1024; idx += 256) {
                    int r = idx >> 4, cc = (idx & 15) << 2;
                    *(float4*)&att[attbase + (size_t)(q0 + r) * T_ + k0 + cc] = z;
                }
            }
            continue;
        }

        {
            const float* ksrc = &g_K[(size_t)(b * T_ + k0) * KVC_ + h * D_];
            const float* vsrc = &g_V[(size_t)(b * T_ + k0) * KVC_ + h * D_];
            for (int idx = tid; idx < 1024; idx += 256) {
                int r = idx >> 4, d = (idx & 15) << 2;
                *(float4*)&Ks[r * PAD + d] = *(const float4*)&ksrc[(size_t)r * KVC_ + d];
                *(float4*)&Vs[r * PAD + d] = *(const float4*)&vsrc[(size_t)r * KVC_ + d];
            }
        }
        __syncthreads();

        float c[4][4];
#pragma unroll
        for (int nt = 0; nt < 4; nt++)
#pragma unroll
            for (int e = 0; e < 4; e++) c[nt][e] = 0.f;
#pragma unroll
        for (int ks2 = 0; ks2 < 8; ks2++) {
            const int d0 = ks2 * 8;
            uint32_t a0 = __float_as_uint(Qs[(row0    ) * PAD + d0 + tig]);
            uint32_t a1 = __float_as_uint(Qs[(row0 + 8) * PAD + d0 + tig]);
            uint32_t a2 = __float_as_uint(Qs[(row0    ) * PAD + d0 + tig + 4]);
            uint32_t a3 = __float_as_uint(Qs[(row0 + 8) * PAD + d0 + tig + 4]);
#pragma unroll
            for (int nt = 0; nt < 4; nt++) {
                const int nc = nbase + nt * 8 + gid;
                uint32_t b0 = __float_as_uint(Ks[nc * PAD + d0 + tig]);
                uint32_t b1 = __float_as_uint(Ks[nc * PAD + d0 + tig + 4]);
                mma_tf32(c[nt], a0, a1, a2, a3, b0, b1);
            }
        }

        const bool dm = (kt == diag);
#pragma unroll
        for (int nt = 0; nt < 4; nt++) {
            const int col  = nbase + nt * 8 + 2 * tig;
            const int colg = k0 + col;
            float v00 = c[nt][0] * 0.125f, v01 = c[nt][1] * 0.125f;
            float v10 = c[nt][2] * 0.125f, v11 = c[nt][3] * 0.125f;
            if (dm) {
                if (colg     > q0 + row0    ) v00 = -1e30f;
                if (colg + 1 > q0 + row0    ) v01 = -1e30f;
                if (colg     > q0 + row0 + 8) v10 = -1e30f;
                if (colg + 1 > q0 + row0 + 8) v11 = -1e30f;
            }
            const float p00 = __expf(v00 - mr0) * li0;
            const float p01 = __expf(v01 - mr0) * li0;
            const float p10 = __expf(v10 - mr1) * li1;
            const float p11 = __expf(v11 - mr1) * li1;
            *(float2*)&Ps[(row0    ) * PAD + col] = make_float2(tf32rn(p00), tf32rn(p01));
            *(float2*)&Ps[(row0 + 8) * PAD + col] = make_float2(tf32rn(p10), tf32rn(p11));
            if (write_att) {
                *(float2*)&att[attbase + (size_t)(q0 + row0    ) * T_ + colg] = make_float2(p00, p01);
                *(float2*)&att[attbase + (size_t)(q0 + row0 + 8) * T_ + colg] = make_float2(p10, p11);
            }
        }
        __syncthreads();

#pragma unroll
        for (int ks2 = 0; ks2 < 8; ks2++) {
            const int kc0 = ks2 * 8;
            uint32_t a0 = __float_as_uint(Ps[(row0    ) * PAD + kc0 + tig]);
            uint32_t a1 = __float_as_uint(Ps[(row0 + 8) * PAD + kc0 + tig]);
            uint32_t a2 = __float_as_uint(Ps[(row0    ) * PAD + kc0 + tig + 4]);
            uint32_t a3 = __float_as_uint(Ps[(row0 + 8) * PAD + kc0 + tig + 4]);
#pragma unroll
            for (int nt = 0; nt < 4; nt++) {
                const int dc = nbase + nt * 8 + gid;
                uint32_t b0 = __float_as_uint(Vs[(kc0 + tig    ) * PAD + dc]);
                uint32_t b1 = __float_as_uint(Vs[(kc0 + tig + 4) * PAD + dc]);
                mma_tf32(yc[nt], a0, a1, a2, a3, b0, b1);
            }
        }
        __syncthreads();
    }

    // write Y as pre-split bf16 hi/lo (feeds gemm_o)
    uint32_t* yhu = (uint32_t*)g_Yh;
    uint32_t* ylu = (uint32_t*)g_Yl;
#pragma unroll
    for (int nt = 0; nt < 4; nt++) {
        const int col = nbase + nt * 8 + 2 * tig;
        const size_t i0 = ((size_t)(b * T_ + q0 + row0    ) * C_ + hq * D_ + col) >> 1;
        const size_t i1 = ((size_t)(b * T_ + q0 + row0 + 8) * C_ + hq * D_ + col) >> 1;
        float h00 = __bfloat162float(__float2bfloat16_rn(yc[nt][0]));
        float h01 = __bfloat162float(__float2bfloat16_rn(yc[nt][1]));
        float h10 = __bfloat162float(__float2bfloat16_rn(yc[nt][2]));
        float h11 = __bfloat162float(__float2bfloat16_rn(yc[nt][3]));
        yhu[i0] = pack_bf2(h00, h01);
        ylu[i0] = pack_bf2(yc[nt][0] - h00, yc[nt][1] - h01);
        yhu[i1] = pack_bf2(h10, h11);
        ylu[i1] = pack_bf2(yc[nt][2] - h10, yc[nt][3] - h11);
    }
}

// ---------------- launch ----------------
#define FIN_SMEM (4 * 64 * PAD * (int)sizeof(float))   // 69,632 B

extern "C" void kernel_launch(void* const* d_in, const int* in_sizes, int n_in,
                              void* d_out, int out_size)
{
    const float* x  = (const float*)d_in[0];
    const float* Wq = (const float*)d_in[1];
    const float* bq = (const float*)d_in[2];
    const float* Wk = (const float*)d_in[3];
    const float* bk = (const float*)d_in[4];
    const float* Wv = (const float*)d_in[5];
    const float* bv = (const float*)d_in[6];
    const float* Wo = (const float*)d_in[7];
    const float* bo = (const float*)d_in[8];

    static float *qp = nullptr, *bcat = nullptr;
    static __nv_bfloat16 *xh, *xl, *wch, *wcl, *woh, *wol;
    if (!qp) {
        cudaGetSymbolAddress((void**)&qp,   g_Q);
        cudaGetSymbolAddress((void**)&bcat, g_bcat);
        cudaGetSymbolAddress((void**)&xh,   g_Xh);
        cudaGetSymbolAddress((void**)&xl,   g_Xl);
        cudaGetSymbolAddress((void**)&wch,  g_Wch);
        cudaGetSymbolAddress((void**)&wcl,  g_Wcl);
        cudaGetSymbolAddress((void**)&woh,  g_Woh);
        cudaGetSymbolAddress((void**)&wol,  g_Wol);
        cudaFuncSetAttribute(attn_finalize_mma,
                             cudaFuncAttributeMaxDynamicSharedMemorySize, FIN_SMEM);
        cudaFuncSetAttribute(gemm_qkv,
                             cudaFuncAttributeMaxDynamicSharedMemorySize, GEMM_SMEM);
        cudaFuncSetAttribute(gemm_o,
                             cudaFuncAttributeMaxDynamicSharedMemorySize, GEMM_SMEM);
    }

    const size_t yElems   = (size_t)N_ * C_;
    const size_t attElems = (size_t)B_ * G_ * HKV_ * T_ * T_;
    float* out = (float*)d_out;
    float* yOut;
    float* attOut;
    int    writeAtt;
    size_t osz = (size_t)out_size;
    if (osz >= yElems + attElems)      { yOut = out; attOut = out + yElems; writeAtt = 1; }
    else if (osz == attElems)          { yOut = qp;  attOut = out;          writeAtt = 1; }
    else                               { yOut = out; attOut = qp;           writeAtt = 0; }

    cudaMemcpyAsync(bcat,             bq, C_   * sizeof(float), cudaMemcpyDeviceToDevice);
    cudaMemcpyAsync(bcat + C_,        bk, KVC_ * sizeof(float), cudaMemcpyDeviceToDevice);
    cudaMemcpyAsync(bcat + C_ + KVC_, bv, KVC_ * sizeof(float), cudaMemcpyDeviceToDevice);

    dim3 blk(256);
    dim3 tb(32, 8);
    split_x<<<(N_ * C_ / 4) / 256, blk>>>(x, xh, xl);
    transpose_split<<<dim3(C_   / 32, C_ / 32), tb>>>(Wq, wch,                          wcl,                          C_, C_);
    transpose_split<<<dim3(KVC_ / 32, C_ / 32), tb>>>(Wk, wch + (size_t)C_ * C_,        wcl + (size_t)C_ * C_,        C_, KVC_);
    transpose_split<<<dim3(KVC_ / 32, C_ / 32), tb>>>(Wv, wch + (size_t)(C_+KVC_) * C_, wcl + (size_t)(C_+KVC_) * C_, C_, KVC_);
    transpose_split<<<dim3(C_   / 32, C_ / 32), tb>>>(Wo, woh, wol, C_, C_);

    gemm_qkv<<<dim3(QKV_ / 128, N_ / 128), blk, GEMM_SMEM>>>();

    attn_stats_mma   <<<dim3(T_ / 64, B_ * HQ_), blk>>>();
    attn_finalize_mma<<<dim3(T_ / 64, B_ * HQ_), blk, FIN_SMEM>>>(attOut, writeAtt);

    gemm_o<<<dim3(C_ / 128, N_ / 128), blk, GEMM_SMEM>>>(bo, yOut);
}

// round 17
// speedup vs baseline: 1.1008x; 1.0367x over previous
// R17 = R15 resubmitted unchanged (3rd attempt): R15/R16 died at GPU
// acquisition (broker pool saturated; failure precedes compilation). The R15
// change-set (cp.async pipelined K/V tiles in both attention kernels) remains
// unmeasured; holding it stable for clean attribution.
#include <cuda_runtime.h>
#include <cuda_bf16.h>
#include <math.h>
#include <stdint.h>

#define B_   4
#define T_   2048
#define C_   1024
#define HQ_  16
#define HKV_ 4
#define D_   64
#define G_   4
#define N_   (B_*T_)        // 8192 rows
#define KVC_ (HKV_*D_)      // 256
#define QKV_ (C_+2*KVC_)    // 1536 concatenated proj cols
#define PAD  68             // attention smem row stride (floats)
#define GKP  40             // gemm smem row stride in bf16 elems
#define TSZ  (64*PAD)       // one attention tile in floats (17,408 B)

// ---------------- scratch (no allocations allowed) ----------------
__device__ float g_Q[(size_t)N_*C_];     // tf32-rounded at producer
__device__ float g_K[(size_t)N_*KVC_];   // tf32-rounded at producer
__device__ float g_V[(size_t)N_*KVC_];   // tf32-rounded at producer
__device__ float g_M[B_*HQ_*T_];
__device__ float g_L[B_*HQ_*T_];
__device__ float g_bcat[QKV_];
__device__ __nv_bfloat16 g_Xh[(size_t)N_*C_], g_Xl[(size_t)N_*C_];
__device__ __nv_bfloat16 g_Yh[(size_t)N_*C_], g_Yl[(size_t)N_*C_];
__device__ __nv_bfloat16 g_Wch[(size_t)QKV_*C_], g_Wcl[(size_t)QKV_*C_];
__device__ __nv_bfloat16 g_Woh[(size_t)C_*C_],   g_Wol[(size_t)C_*C_];

// ---------------- helpers ----------------
__device__ __forceinline__ void mma_tf32(float c[4],
    uint32_t a0, uint32_t a1, uint32_t a2, uint32_t a3,
    uint32_t b0, uint32_t b1)
{
    asm volatile(
        "mma.sync.aligned.m16n8k8.row.col.f32.tf32.tf32.f32 "
        "{%0,%1,%2,%3}, {%4,%5,%6,%7}, {%8,%9}, {%0,%1,%2,%3};\n"
        : "+f"(c[0]), "+f"(c[1]), "+f"(c[2]), "+f"(c[3])
        : "r"(a0), "r"(a1), "r"(a2), "r"(a3), "r"(b0), "r"(b1));
}
__device__ __forceinline__ void mma_bf16(float c[4],
    uint32_t a0, uint32_t a1, uint32_t a2, uint32_t a3,
    uint32_t b0, uint32_t b1)
{
    asm volatile(
        "mma.sync.aligned.m16n8k16.row.col.f32.bf16.bf16.f32 "
        "{%0,%1,%2,%3}, {%4,%5,%6,%7}, {%8,%9}, {%0,%1,%2,%3};\n"
        : "+f"(c[0]), "+f"(c[1]), "+f"(c[2]), "+f"(c[3])
        : "r"(a0), "r"(a1), "r"(a2), "r"(a3), "r"(b0), "r"(b1));
}
__device__ __forceinline__ float tf32rn(float x)
{
    uint32_t u;
    asm("cvt.rna.tf32.f32 %0, %1;" : "=r"(u) : "f"(x));
    return __uint_as_float(u);
}
__device__ __forceinline__ uint32_t pack_bf2(float x, float y)
{
    __nv_bfloat162 t = __floats2bfloat162_rn(x, y);
    return *(uint32_t*)&t;
}
__device__ __forceinline__ void cp16(void* smem_dst, const void* gmem_src)
{
    uint32_t s = (uint32_t)__cvta_generic_to_shared(smem_dst);
    asm volatile("cp.async.cg.shared.global [%0], [%1], 16;\n" :: "r"(s), "l"(gmem_src));
}
#define CP_COMMIT()  asm volatile("cp.async.commit_group;\n" ::: "memory")
#define CP_WAIT(n)   asm volatile("cp.async.wait_group %0;\n" :: "n"(n) : "memory")

// ---------------- x -> bf16 hi/lo split ----------------
__global__ __launch_bounds__(256) void split_x(const float* __restrict__ X,
                                               __nv_bfloat16* __restrict__ Xh,
                                               __nv_bfloat16* __restrict__ Xl)
{
    const int idx = blockIdx.x * 256 + threadIdx.x;
    float4 v = ((const float4*)X)[idx];
    float hx = __bfloat162float(__float2bfloat16_rn(v.x));
    float hy = __bfloat162float(__float2bfloat16_rn(v.y));
    float hz = __bfloat162float(__float2bfloat16_rn(v.z));
    float hw = __bfloat162float(__float2bfloat16_rn(v.w));
    ((uint2*)Xh)[idx] = make_uint2(pack_bf2(hx, hy), pack_bf2(hz, hw));
    ((uint2*)Xl)[idx] = make_uint2(pack_bf2(v.x - hx, v.y - hy), pack_bf2(v.z - hz, v.w - hw));
}

// ---------------- weight prep: transpose + bf16 hi/lo split ----------------
__global__ void transpose_split(const float* __restrict__ W,
                                __nv_bfloat16* __restrict__ Th,
                                __nv_bfloat16* __restrict__ Tl,
                                int K, int N)
{
    __shared__ float s[32][33];
    const int n0 = blockIdx.x * 32, k0 = blockIdx.y * 32;
    const int tx = threadIdx.x, ty = threadIdx.y;
#pragma unroll
    for (int i = 0; i < 32; i += 8)
        s[ty + i][tx] = W[(size_t)(k0 + ty + i) * N + n0 + tx];
    __syncthreads();
#pragma unroll
    for (int i = 0; i < 32; i += 8) {
        float v = s[tx][ty + i];
        __nv_bfloat16 h = __float2bfloat16_rn(v);
        __nv_bfloat16 l = __float2bfloat16_rn(v - __bfloat162float(h));
        Th[(size_t)(n0 + ty + i) * K + k0 + tx] = h;
        Tl[(size_t)(n0 + ty + i) * K + k0 + tx] = l;
    }
}

// ---------------- cp.async double-buffered bf16x3 GEMM mainloop ----------------
#define GEMM_SMEM (2 * 4 * 128 * GKP * (int)sizeof(__nv_bfloat16))

#define GEMM_CORE(Ath, Atl, Bth, Btl)                                             \
    extern __shared__ __nv_bfloat16 smg[];                                        \
    const int SS = 128 * GKP;                                                     \
    __nv_bfloat16 *Ahb = smg,          *Alb = smg + 2 * SS;                       \
    __nv_bfloat16 *Bhb = smg + 4 * SS, *Blb = smg + 6 * SS;                       \
    const int tid  = threadIdx.x;                                                 \
    const int w    = tid >> 5;                                                    \
    const int lane = tid & 31;                                                    \
    const int gid  = lane >> 2;                                                   \
    const int tig  = lane & 3;                                                    \
    const int mw   = w & 3;                                                       \
    const int nw   = w >> 2;                                                      \
    const int cB0  = nw * 64;                                                     \
    auto pref = [&](int st, int kbase) {                                          \
        _Pragma("unroll")                                                         \
        for (int i = 0; i < 2; i++) {                                             \
            int idx8 = tid + i * 256;                                             \
            int r = idx8 >> 2, k8 = (idx8 & 3) << 3;                              \
            int so = st * SS + r * GKP + k8;                                      \
            cp16(&Ahb[so], &Ath[(size_t)(row0 + r) * 1024 + kbase + k8]);         \
            cp16(&Alb[so], &Atl[(size_t)(row0 + r) * 1024 + kbase + k8]);         \
            cp16(&Bhb[so], &Bth[(size_t)(col0 + r) * 1024 + kbase + k8]);         \
            cp16(&Blb[so], &Btl[(size_t)(col0 + r) * 1024 + kbase + k8]);         \
        }                                                                         \
    };                                                                            \
    float acc[2][8][4];                                                           \
    _Pragma("unroll")                                                             \
    for (int m = 0; m < 2; m++)                                                   \
        _Pragma("unroll")                                                         \
        for (int n = 0; n < 8; n++)                                               \
            _Pragma("unroll")                                                     \
            for (int e = 0; e < 4; e++) acc[m][n][e] = 0.f;                       \
    pref(0, 0);                                                                   \
    CP_COMMIT();                                                                  \
    for (int it = 0; it < 32; it++) {                                             \
        if (it + 1 < 32) { pref((it + 1) & 1, (it + 1) * 32); CP_COMMIT(); }      \
        if (it + 1 < 32) CP_WAIT(1); else CP_WAIT(0);                             \
        __syncthreads();                                                          \
        const int st = it & 1;                                                    \
        uint32_t* Ahu = (uint32_t*)(Ahb + st * SS);                               \
        uint32_t* Alu = (uint32_t*)(Alb + st * SS);                               \
        uint32_t* Bhu = (uint32_t*)(Bhb + st * SS);                               \
        uint32_t* Blu = (uint32_t*)(Blb + st * SS);                               \
        _Pragma("unroll")                                                         \
        for (int kk = 0; kk < 32; kk += 16) {                                     \
            const int kw = (kk >> 1) + tig;                                       \
            uint32_t ah[2][4], al[2][4];                                          \
            _Pragma("unroll")                                                     \
            for (int m = 0; m < 2; m++) {                                         \
                const int rm = mw * 32 + m * 16 + gid;                            \
                ah[m][0] = Ahu[ rm      * (GKP/2) + kw];                          \
                ah[m][1] = Ahu[(rm + 8) * (GKP/2) + kw];                          \
                ah[m][2] = Ahu[ rm      * (GKP/2) + kw + 4];                      \
                ah[m][3] = Ahu[(rm + 8) * (GKP/2) + kw + 4];                      \
                al[m][0] = Alu[ rm      * (GKP/2) + kw];                          \
                al[m][1] = Alu[(rm + 8) * (GKP/2) + kw];                          \
                al[m][2] = Alu[ rm      * (GKP/2) + kw + 4];                      \
                al[m][3] = Alu[(rm + 8) * (GKP/2) + kw + 4];                      \
            }                                                                     \
            _Pragma("unroll")                                                     \
            for (int n = 0; n < 8; n++) {                                         \
                const int cn = (cB0 + n * 8 + gid) * (GKP/2) + kw;                \
                uint32_t bh0 = Bhu[cn], bh1 = Bhu[cn + 4];                        \
                uint32_t bl0 = Blu[cn], bl1 = Blu[cn + 4];                        \
                mma_bf16(acc[0][n], ah[0][0], ah[0][1], ah[0][2], ah[0][3], bh0, bh1); \
                mma_bf16(acc[1][n], ah[1][0], ah[1][1], ah[1][2], ah[1][3], bh0, bh1); \
                mma_bf16(acc[0][n], ah[0][0], ah[0][1], ah[0][2], ah[0][3], bl0, bl1); \
                mma_bf16(acc[1][n], ah[1][0], ah[1][1], ah[1][2], ah[1][3], bl0, bl1); \
                mma_bf16(acc[0][n], al[0][0], al[0][1], al[0][2], al[0][3], bh0, bh1); \
                mma_bf16(acc[1][n], al[1][0], al[1][1], al[1][2], al[1][3], bh0, bh1); \
            }                                                                     \
        }                                                                         \
        __syncthreads();                                                          \
    }

// fused QKV projection; epilogue tf32-rounds
__global__ __launch_bounds__(256) void gemm_qkv()
{
    const int row0 = blockIdx.y * 128, col0 = blockIdx.x * 128;
    GEMM_CORE(g_Xh, g_Xl, g_Wch, g_Wcl)

    float* dst; int nd, cofs;
    if (col0 < C_)              { dst = g_Q; nd = C_;   cofs = 0; }
    else if (col0 < C_ + KVC_)  { dst = g_K; nd = KVC_; cofs = C_; }
    else                        { dst = g_V; nd = KVC_; cofs = C_ + KVC_; }

#pragma unroll
    for (int m = 0; m < 2; m++) {
        const int row = row0 + mw * 32 + m * 16 + gid;
#pragma unroll
        for (int n = 0; n < 8; n++) {
            const int col = col0 + cB0 + n * 8 + 2 * tig;
            const float b0 = g_bcat[col], b1 = g_bcat[col + 1];
            const int cc = col - cofs;
            *(float2*)&dst[(size_t)row * nd + cc] =
                make_float2(tf32rn(acc[m][n][0] + b0), tf32rn(acc[m][n][1] + b1));
            *(float2*)&dst[(size_t)(row + 8) * nd + cc] =
                make_float2(tf32rn(acc[m][n][2] + b0), tf32rn(acc[m][n][3] + b1));
        }
    }
}

// output projection
__global__ __launch_bounds__(256) void gemm_o(const float* __restrict__ bias,
                                              float* __restrict__ out)
{
    const int row0 = blockIdx.y * 128, col0 = blockIdx.x * 128;
    GEMM_CORE(g_Yh, g_Yl, g_Woh, g_Wol)

#pragma unroll
    for (int m = 0; m < 2; m++) {
        const int row = row0 + mw * 32 + m * 16 + gid;
#pragma unroll
        for (int n = 0; n < 8; n++) {
            const int col = col0 + cB0 + n * 8 + 2 * tig;
            const float b0 = bias[col], b1 = bias[col + 1];
            *(float2*)&out[(size_t)row * C_ + col] =
                make_float2(acc[m][n][0] + b0, acc[m][n][1] + b1);
            *(float2*)&out[(size_t)(row + 8) * C_ + col] =
                make_float2(acc[m][n][2] + b0, acc[m][n][3] + b1);
        }
    }
}

// ---------------- attention pass 1: pipelined K, row max + sumexp ----------------
#define STATS_SMEM (3 * TSZ * (int)sizeof(float))   // 52,224 B
__global__ __launch_bounds__(256) void attn_stats_mma()
{
    extern __shared__ float sms[];
    float* Qs = sms;          // 1 tile
    float* Kb = sms + TSZ;    // 2 stages
    __shared__ float redM[2][64];
    __shared__ float redL[2][64];

    const int tid  = threadIdx.x;
    const int w    = tid >> 5;
    const int lane = tid & 31;
    const int gid  = lane >> 2;
    const int tig  = lane & 3;
    const int mstrip = w & 3;
    const int nhalf  = w >> 2;
    const int row0  = mstrip * 16 + gid;
    const int nbase = nhalf * 32;

    const int bh = blockIdx.y;
    const int b  = bh >> 4, hq = bh & 15, h = hq >> 2;
    const int q0 = blockIdx.x * 64;
    const int diag = q0 >> 6;

    auto prefK = [&](int st, int kt) {
        const float* ksrc = &g_K[(size_t)(b * T_ + kt * 64) * KVC_ + h * D_];
#pragma unroll
        for (int i = 0; i < 4; i++) {
            int idx = tid + i * 256;                 // 0..1023
            int r = idx >> 4, c4 = (idx & 15) << 2;
            cp16(&Kb[st * TSZ + r * PAD + c4], &ksrc[(size_t)r * KVC_ + c4]);
        }
    };

    {
        const float* src = &g_Q[(size_t)(b * T_ + q0) * C_ + hq * D_];
        for (int idx = tid; idx < 1024; idx += 256) {
            int r = idx >> 4, d = (idx & 15) << 2;
            *(float4*)&Qs[r * PAD + d] = *(const float4*)&src[(size_t)r * C_ + d];
        }
    }
    prefK(0, 0);
    CP_COMMIT();

    float runm0 = -1e30f, runs0 = 0.f, runm1 = -1e30f, runs1 = 0.f;

    for (int kt = 0; kt <= diag; kt++) {
        if (kt < diag) { prefK((kt + 1) & 1, kt + 1); CP_COMMIT(); }
        if (kt < diag) CP_WAIT(1); else CP_WAIT(0);
        __syncthreads();
        const float* Ks = Kb + (kt & 1) * TSZ;
        const int k0 = kt * 64;

        float c[4][4];
#pragma unroll
        for (int nt = 0; nt < 4; nt++)
#pragma unroll
            for (int e = 0; e < 4; e++) c[nt][e] = 0.f;

#pragma unroll
        for (int ks2 = 0; ks2 < 8; ks2++) {
            const int d0 = ks2 * 8;
            uint32_t a0 = __float_as_uint(Qs[(row0    ) * PAD + d0 + tig]);
            uint32_t a1 = __float_as_uint(Qs[(row0 + 8) * PAD + d0 + tig]);
            uint32_t a2 = __float_as_uint(Qs[(row0    ) * PAD + d0 + tig + 4]);
            uint32_t a3 = __float_as_uint(Qs[(row0 + 8) * PAD + d0 + tig + 4]);
#pragma unroll
            for (int nt = 0; nt < 4; nt++) {
                const int nc = nbase + nt * 8 + gid;
                uint32_t b0 = __float_as_uint(Ks[nc * PAD + d0 + tig]);
                uint32_t b1 = __float_as_uint(Ks[nc * PAD + d0 + tig + 4]);
                mma_tf32(c[nt], a0, a1, a2, a3, b0, b1);
            }
        }

        const bool dm = (kt == diag);
#pragma unroll
        for (int nt = 0; nt < 4; nt++) {
            const int colb = k0 + nbase + nt * 8 + 2 * tig;
#pragma unroll
            for (int e = 0; e < 2; e++) {
                float v0 = c[nt][e]     * 0.125f;
                float v1 = c[nt][2 + e] * 0.125f;
                if (dm && colb + e > q0 + row0    ) v0 = -1e30f;
                if (dm && colb + e > q0 + row0 + 8) v1 = -1e30f;
                c[nt][e] = v0; c[nt][2 + e] = v1;
            }
        }

        float m0 = c[0][0], m1 = c[0][2];
#pragma unroll
        for (int nt = 0; nt < 4; nt++) {
            m0 = fmaxf(m0, fmaxf(c[nt][0], c[nt][1]));
            m1 = fmaxf(m1, fmaxf(c[nt][2], c[nt][3]));
        }
        m0 = fmaxf(m0, __shfl_xor_sync(0xffffffffu, m0, 1));
        m0 = fmaxf(m0, __shfl_xor_sync(0xffffffffu, m0, 2));
        m1 = fmaxf(m1, __shfl_xor_sync(0xffffffffu, m1, 1));
        m1 = fmaxf(m1, __shfl_xor_sync(0xffffffffu, m1, 2));

        const float nm0 = fmaxf(runm0, m0);
        const float nm1 = fmaxf(runm1, m1);
        float s0 = 0.f, s1 = 0.f;
#pragma unroll
        for (int nt = 0; nt < 4; nt++) {
            s0 += __expf(c[nt][0] - nm0) + __expf(c[nt][1] - nm0);
            s1 += __expf(c[nt][2] - nm1) + __expf(c[nt][3] - nm1);
        }
        s0 += __shfl_xor_sync(0xffffffffu, s0, 1);
        s0 += __shfl_xor_sync(0xffffffffu, s0, 2);
        s1 += __shfl_xor_sync(0xffffffffu, s1, 1);
        s1 += __shfl_xor_sync(0xffffffffu, s1, 2);

        runs0 = runs0 * __expf(runm0 - nm0) + s0;  runm0 = nm0;
        runs1 = runs1 * __expf(runm1 - nm1) + s1;  runm1 = nm1;
        __syncthreads();
    }

    if (tig == 0) {
        redM[nhalf][row0]     = runm0;  redL[nhalf][row0]     = runs0;
        redM[nhalf][row0 + 8] = runm1;  redL[nhalf][row0 + 8] = runs1;
    }
    __syncthreads();
    if (nhalf == 0 && tig == 0) {
#pragma unroll
        for (int rr = 0; rr < 2; rr++) {
            const int r = row0 + rr * 8;
            const float ma = redM[0][r], mb = redM[1][r];
            const float m  = fmaxf(ma, mb);
            const float l  = redL[0][r] * __expf(ma - m) + redL[1][r] * __expf(mb - m);
            g_M[bh * T_ + q0 + r] = m;
            g_L[bh * T_ + q0 + r] = l;
        }
    }
}

// ---------------- attention pass 2: pipelined K+V, 64-row tiles ----------------
#define FIN_SMEM (6 * TSZ * (int)sizeof(float))   // 104,448 B (Q, K x2, V x2, P)
__global__ __launch_bounds__(256) void attn_finalize_mma(float* __restrict__ att,
                                                         int write_att)
{
    extern __shared__ float smdyn[];
    float* Qs = smdyn;               // 1 tile
    float* Kb = smdyn + TSZ;         // 2 stages
    float* Vb = smdyn + 3 * TSZ;     // 2 stages
    float* Ps = smdyn + 5 * TSZ;     // 1 tile

    const int tid  = threadIdx.x;
    const int w    = tid >> 5;
    const int lane = tid & 31;
    const int gid  = lane >> 2;
    const int tig  = lane & 3;
    const int mstrip = w & 3;
    const int nhalf  = w >> 2;
    const int row0  = mstrip * 16 + gid;
    const int nbase = nhalf * 32;

    const int bh = blockIdx.y;
    const int b  = bh >> 4, hq = bh & 15, h = hq >> 2, g = hq & 3;
    const int q0 = blockIdx.x * 64;
    const int diag = q0 >> 6;
    const size_t attbase = (size_t)((b * G_ + g) * HKV_ + h) * T_ * T_;

    auto prefKV = [&](int st, int kt) {
        const float* ksrc = &g_K[(size_t)(b * T_ + kt * 64) * KVC_ + h * D_];
        const float* vsrc = &g_V[(size_t)(b * T_ + kt * 64) * KVC_ + h * D_];
#pragma unroll
        for (int i = 0; i < 4; i++) {
            int idx = tid + i * 256;
            int r = idx >> 4, c4 = (idx & 15) << 2;
            cp16(&Kb[st * TSZ + r * PAD + c4], &ksrc[(size_t)r * KVC_ + c4]);
            cp16(&Vb[st * TSZ + r * PAD + c4], &vsrc[(size_t)r * KVC_ + c4]);
        }
    };

    {
        const float* src = &g_Q[(size_t)(b * T_ + q0) * C_ + hq * D_];
        for (int idx = tid; idx < 1024; idx += 256) {
            int r = idx >> 4, d = (idx & 15) << 2;
            *(float4*)&Qs[r * PAD + d] = *(const float4*)&src[(size_t)r * C_ + d];
        }
    }
    prefKV(0, 0);
    CP_COMMIT();

    const float mr0 = g_M[bh * T_ + q0 + row0];
    const float li0 = 1.f / g_L[bh * T_ + q0 + row0];
    const float mr1 = g_M[bh * T_ + q0 + row0 + 8];
    const float li1 = 1.f / g_L[bh * T_ + q0 + row0 + 8];

    float yc[4][4];
#pragma unroll
    for (int nt = 0; nt < 4; nt++)
#pragma unroll
        for (int e = 0; e < 4; e++) yc[nt][e] = 0.f;

    for (int kt = 0; kt <= diag; kt++) {
        if (kt < diag) { prefKV((kt + 1) & 1, kt + 1); CP_COMMIT(); }
        if (kt < diag) CP_WAIT(1); else CP_WAIT(0);
        __syncthreads();
        const float* Ks = Kb + (kt & 1) * TSZ;
        const float* Vs = Vb + (kt & 1) * TSZ;
        const int k0 = kt * 64;

        float c[4][4];
#pragma unroll
        for (int nt = 0; nt < 4; nt++)
#pragma unroll
            for (int e = 0; e < 4; e++) c[nt][e] = 0.f;
#pragma unroll
        for (int ks2 = 0; ks2 < 8; ks2++) {
            const int d0 = ks2 * 8;
            uint32_t a0 = __float_as_uint(Qs[(row0    ) * PAD + d0 + tig]);
            uint32_t a1 = __float_as_uint(Qs[(row0 + 8) * PAD + d0 + tig]);
            uint32_t a2 = __float_as_uint(Qs[(row0    ) * PAD + d0 + tig + 4]);
            uint32_t a3 = __float_as_uint(Qs[(row0 + 8) * PAD + d0 + tig + 4]);
#pragma unroll
            for (int nt = 0; nt < 4; nt++) {
                const int nc = nbase + nt * 8 + gid;
                uint32_t b0 = __float_as_uint(Ks[nc * PAD + d0 + tig]);
                uint32_t b1 = __float_as_uint(Ks[nc * PAD + d0 + tig + 4]);
                mma_tf32(c[nt], a0, a1, a2, a3, b0, b1);
            }
        }

        const bool dm = (kt == diag);
#pragma unroll
        for (int nt = 0; nt < 4; nt++) {
            const int col  = nbase + nt * 8 + 2 * tig;
            const int colg = k0 + col;
            float v00 = c[nt][0] * 0.125f, v01 = c[nt][1] * 0.125f;
            float v10 = c[nt][2] * 0.125f, v11 = c[nt][3] * 0.125f;
            if (dm) {
                if (colg     > q0 + row0    ) v00 = -1e30f;
                if (colg + 1 > q0 + row0    ) v01 = -1e30f;
                if (colg     > q0 + row0 + 8) v10 = -1e30f;
                if (colg + 1 > q0 + row0 + 8) v11 = -1e30f;
            }
            const float p00 = __expf(v00 - mr0) * li0;
            const float p01 = __expf(v01 - mr0) * li0;
            const float p10 = __expf(v10 - mr1) * li1;
            const float p11 = __expf(v11 - mr1) * li1;
            *(float2*)&Ps[(row0    ) * PAD + col] = make_float2(tf32rn(p00), tf32rn(p01));
            *(float2*)&Ps[(row0 + 8) * PAD + col] = make_float2(tf32rn(p10), tf32rn(p11));
            if (write_att) {
                *(float2*)&att[attbase + (size_t)(q0 + row0    ) * T_ + colg] = make_float2(p00, p01);
                *(float2*)&att[attbase + (size_t)(q0 + row0 + 8) * T_ + colg] = make_float2(p10, p11);
            }
        }
        __syncthreads();

#pragma unroll
        for (int ks2 = 0; ks2 < 8; ks2++) {
            const int kc0 = ks2 * 8;
            uint32_t a0 = __float_as_uint(Ps[(row0    ) * PAD + kc0 + tig]);
            uint32_t a1 = __float_as_uint(Ps[(row0 + 8) * PAD + kc0 + tig]);
            uint32_t a2 = __float_as_uint(Ps[(row0    ) * PAD + kc0 + tig + 4]);
            uint32_t a3 = __float_as_uint(Ps[(row0 + 8) * PAD + kc0 + tig + 4]);
#pragma unroll
            for (int nt = 0; nt < 4; nt++) {
                const int dc = nbase + nt * 8 + gid;
                uint32_t b0 = __float_as_uint(Vs[(kc0 + tig    ) * PAD + dc]);
                uint32_t b1 = __float_as_uint(Vs[(kc0 + tig + 4) * PAD + dc]);
                mma_tf32(yc[nt], a0, a1, a2, a3, b0, b1);
            }
        }
        __syncthreads();
    }

    // fully-masked tiles: exact zeros (d_out is poisoned)
    if (write_att) {
        for (int kt = diag + 1; kt < T_ / 64; kt++) {
            const int k0 = kt * 64;
            const float4 z = make_float4(0.f, 0.f, 0.f, 0.f);
            for (int idx = tid; idx < 1024; idx += 256) {
                int r = idx >> 4, cc = (idx & 15) << 2;
                *(float4*)&att[attbase + (size_t)(q0 + r) * T_ + k0 + cc] = z;
            }
        }
    }

    // write Y as pre-split bf16 hi/lo (feeds gemm_o)
    uint32_t* yhu = (uint32_t*)g_Yh;
    uint32_t* ylu = (uint32_t*)g_Yl;
#pragma unroll
    for (int nt = 0; nt < 4; nt++) {
        const int col = nbase + nt * 8 + 2 * tig;
        const size_t i0 = ((size_t)(b * T_ + q0 + row0    ) * C_ + hq * D_ + col) >> 1;
        const size_t i1 = ((size_t)(b * T_ + q0 + row0 + 8) * C_ + hq * D_ + col) >> 1;
        float h00 = __bfloat162float(__float2bfloat16_rn(yc[nt][0]));
        float h01 = __bfloat162float(__float2bfloat16_rn(yc[nt][1]));
        float h10 = __bfloat162float(__float2bfloat16_rn(yc[nt][2]));
        float h11 = __bfloat162float(__float2bfloat16_rn(yc[nt][3]));
        yhu[i0] = pack_bf2(h00, h01);
        ylu[i0] = pack_bf2(yc[nt][0] - h00, yc[nt][1] - h01);
        yhu[i1] = pack_bf2(h10, h11);
        ylu[i1] = pack_bf2(yc[nt][2] - h10, yc[nt][3] - h11);
    }
}

// ---------------- launch ----------------
extern "C" void kernel_launch(void* const* d_in, const int* in_sizes, int n_in,
                              void* d_out, int out_size)
{
    const float* x  = (const float*)d_in[0];
    const float* Wq = (const float*)d_in[1];
    const float* bq = (const float*)d_in[2];
    const float* Wk = (const float*)d_in[3];
    const float* bk = (const float*)d_in[4];
    const float* Wv = (const float*)d_in[5];
    const float* bv = (const float*)d_in[6];
    const float* Wo = (const float*)d_in[7];
    const float* bo = (const float*)d_in[8];

    static float *qp = nullptr, *bcat = nullptr;
    static __nv_bfloat16 *xh, *xl, *wch, *wcl, *woh, *wol;
    if (!qp) {
        cudaGetSymbolAddress((void**)&qp,   g_Q);
        cudaGetSymbolAddress((void**)&bcat, g_bcat);
        cudaGetSymbolAddress((void**)&xh,   g_Xh);
        cudaGetSymbolAddress((void**)&xl,   g_Xl);
        cudaGetSymbolAddress((void**)&wch,  g_Wch);
        cudaGetSymbolAddress((void**)&wcl,  g_Wcl);
        cudaGetSymbolAddress((void**)&woh,  g_Woh);
        cudaGetSymbolAddress((void**)&wol,  g_Wol);
        cudaFuncSetAttribute(attn_stats_mma,
                             cudaFuncAttributeMaxDynamicSharedMemorySize, STATS_SMEM);
        cudaFuncSetAttribute(attn_finalize_mma,
                             cudaFuncAttributeMaxDynamicSharedMemorySize, FIN_SMEM);
        cudaFuncSetAttribute(gemm_qkv,
                             cudaFuncAttributeMaxDynamicSharedMemorySize, GEMM_SMEM);
        cudaFuncSetAttribute(gemm_o,
                             cudaFuncAttributeMaxDynamicSharedMemorySize, GEMM_SMEM);
    }

    const size_t yElems   = (size_t)N_ * C_;
    const size_t attElems = (size_t)B_ * G_ * HKV_ * T_ * T_;
    float* out = (float*)d_out;
    float* yOut;
    float* attOut;
    int    writeAtt;
    size_t osz = (size_t)out_size;
    if (osz >= yElems + attElems)      { yOut = out; attOut = out + yElems; writeAtt = 1; }
    else if (osz == attElems)          { yOut = qp;  attOut = out;          writeAtt = 1; }
    else                               { yOut = out; attOut = qp;           writeAtt = 0; }

    cudaMemcpyAsync(bcat,             bq, C_   * sizeof(float), cudaMemcpyDeviceToDevice);
    cudaMemcpyAsync(bcat + C_,        bk, KVC_ * sizeof(float), cudaMemcpyDeviceToDevice);
    cudaMemcpyAsync(bcat + C_ + KVC_, bv, KVC_ * sizeof(float), cudaMemcpyDeviceToDevice);

    dim3 blk(256);
    dim3 tb(32, 8);
    split_x<<<(N_ * C_ / 4) / 256, blk>>>(x, xh, xl);
    transpose_split<<<dim3(C_   / 32, C_ / 32), tb>>>(Wq, wch,                          wcl,                          C_, C_);
    transpose_split<<<dim3(KVC_ / 32, C_ / 32), tb>>>(Wk, wch + (size_t)C_ * C_,        wcl + (size_t)C_ * C_,        C_, KVC_);
    transpose_split<<<dim3(KVC_ / 32, C_ / 32), tb>>>(Wv, wch + (size_t)(C_+KVC_) * C_, wcl + (size_t)(C_+KVC_) * C_, C_, KVC_);
    transpose_split<<<dim3(C_   / 32, C_ / 32), tb>>>(Wo, woh, wol, C_, C_);

    gemm_qkv<<<dim3(QKV_ / 128, N_ / 128), blk, GEMM_SMEM>>>();

    attn_stats_mma   <<<dim3(T_ / 64, B_ * HQ_), blk, STATS_SMEM>>>();
    attn_finalize_mma<<<dim3(T_ / 64, B_ * HQ_), blk, FIN_SMEM>>>(attOut, writeAtt);

    gemm_o<<<dim3(C_ / 128, N_ / 128), blk, GEMM_SMEM>>>(bo, yOut);
}